// round 15
// baseline (speedup 1.0000x reference)
#include <cuda_runtime.h>
#include <math.h>

#define H   1024
#define H4  4096
#define SL  64
#define TL  64
#define V   32000
#define NC  128
#define TPB 256

// ---------- device scratch (statics only; no allocation) ----------
__device__ __align__(16) float g_xe[SL * H];
__device__ __align__(16) float g_xd[TL * H];
__device__ __align__(16) float g_xih[SL * H4];
__device__ __align__(16) float g_w1x[TL * H];
__device__ __align__(16) float g_gx[TL * H4];
__device__ __align__(16) float g_eo[SL * H];    // encoder outputs
__device__ __align__(16) float g_ep[SL * H];    // att_Wu@enc_outs + att_bu
__device__ __align__(16) float g_cp[SL * H];    // W1c @ enc_outs[s]
__device__ __align__(16) float g_Qt[SL * H4];   // dec_Wih @ cp[s]
__device__ __align__(16) float g_pre[TL * H];
__device__ __align__(16) float g_h[2][H];
__device__ __align__(16) float g_c[H];
__device__ __align__(16) float g_part[SL * NC];
__device__ int      g_dtok[TL];
__device__ unsigned g_flags[NC * 8];

// ---------- helpers ----------
__device__ __forceinline__ float sigf(float x) { return 1.f / (1.f + expf(-x)); }
__device__ __forceinline__ float dot4(float4 a, float4 b, float acc) {
    acc = fmaf(a.x, b.x, acc); acc = fmaf(a.y, b.y, acc);
    acc = fmaf(a.z, b.z, acc); acc = fmaf(a.w, b.w, acc);
    return acc;
}
__device__ __forceinline__ float warp_sum(float v) {
#pragma unroll
    for (int o = 16; o; o >>= 1) v += __shfl_down_sync(0xffffffffu, v, o);
    return v;
}
__device__ __forceinline__ void gridbar(int cta, unsigned gen) {
    __syncthreads();
    if (threadIdx.x == 0) {
        __threadfence();
        *((volatile unsigned*)&g_flags[cta << 3]) = gen;
    }
    if (threadIdx.x < NC)
        while (*((volatile unsigned*)&g_flags[threadIdx.x << 3]) < gen) {}
    __threadfence();
    __syncthreads();
}

// ---------- init ----------
__global__ void k_init(const int* __restrict__ tgt) {
    int i = threadIdx.x;
    if (i < H)  { g_h[0][i] = 0.f; g_c[i] = 0.f; }
    if (i < TL) g_dtok[i] = i ? tgt[i - 1] : 0;   // BOS_ID = 0
    if (i < NC) g_flags[i << 3] = 0u;
}

__global__ void k_gather(const float* __restrict__ emb, const int* __restrict__ toks,
                         float* __restrict__ X) {
    int t = blockIdx.x;
    const float* s = emb + (size_t)toks[t] * H;
    for (int i = threadIdx.x; i < H; i += blockDim.x) X[t * H + i] = s[i];
}

// ---------- generic M=64 GEMM: C[m][n0+n] = A[m][:] . B[n0+n][:] + b1 + b2 ----------
__global__ void __launch_bounds__(TPB) gemm64(
    const float* __restrict__ A, int lda, const float* __restrict__ B, int ldb,
    const float* __restrict__ b1, const float* __restrict__ b2,
    float* __restrict__ C, int ldc, int K)
{
    __shared__ __align__(16) float As[32][68], Bs[32][68];
    const int n0 = blockIdx.x << 6, tid = threadIdx.x;
    const int ti = tid & 15, tj = tid >> 4;
    float acc[4][4] = {};
    for (int k0 = 0; k0 < K; k0 += 32) {
#pragma unroll 4
        for (int i = tid; i < 2048; i += TPB) {
            int m = i >> 5, kk = i & 31;
            As[kk][((m & 15) << 2) + (m >> 4)] = A[(size_t)m * lda + k0 + kk];
            Bs[kk][((m & 15) << 2) + (m >> 4)] = B[(size_t)(n0 + m) * ldb + k0 + kk];
        }
        __syncthreads();
#pragma unroll
        for (int kk = 0; kk < 32; kk++) {
            float4 a = *(const float4*)&As[kk][ti << 2];
            float4 b = *(const float4*)&Bs[kk][tj << 2];
            acc[0][0] = fmaf(a.x, b.x, acc[0][0]); acc[0][1] = fmaf(a.x, b.y, acc[0][1]);
            acc[0][2] = fmaf(a.x, b.z, acc[0][2]); acc[0][3] = fmaf(a.x, b.w, acc[0][3]);
            acc[1][0] = fmaf(a.y, b.x, acc[1][0]); acc[1][1] = fmaf(a.y, b.y, acc[1][1]);
            acc[1][2] = fmaf(a.y, b.z, acc[1][2]); acc[1][3] = fmaf(a.y, b.w, acc[1][3]);
            acc[2][0] = fmaf(a.z, b.x, acc[2][0]); acc[2][1] = fmaf(a.z, b.y, acc[2][1]);
            acc[2][2] = fmaf(a.z, b.z, acc[2][2]); acc[2][3] = fmaf(a.z, b.w, acc[2][3]);
            acc[3][0] = fmaf(a.w, b.x, acc[3][0]); acc[3][1] = fmaf(a.w, b.y, acc[3][1]);
            acc[3][2] = fmaf(a.w, b.z, acc[3][2]); acc[3][3] = fmaf(a.w, b.w, acc[3][3]);
        }
        __syncthreads();
    }
#pragma unroll
    for (int nj = 0; nj < 4; nj++) {
        int n = n0 + tj + (nj << 4);
        float bb = (b1 ? b1[n] : 0.f) + (b2 ? b2[n] : 0.f);
#pragma unroll
        for (int mi = 0; mi < 4; mi++)
            C[(size_t)(ti + (mi << 4)) * ldc + n] = acc[mi][nj] + bb;
    }
}

// ---------- encoder: persistent, smem-resident Whh, 1 barrier/step ----------
__global__ void __launch_bounds__(TPB, 1) k_enc(const float* __restrict__ Whh) {
    extern __shared__ float sm[];
    float* sW = sm;            // 32 rows x 1024
    float* sh = sm + 32 * H;   // 1024
    __shared__ float sg[32];
    const int cta = blockIdx.x, tid = threadIdx.x, w = tid >> 5, lane = tid & 31;
    for (int i = tid; i < 8192; i += TPB) {
        int lr = i >> 8, c4 = i & 255, g = lr >> 3, k = lr & 7;
        *(float4*)(sW + lr * H + (c4 << 2)) =
            *(const float4*)(Whh + (((size_t)((g << 10) + (cta << 3) + k)) << 10) + (c4 << 2));
    }
    unsigned gen = *((volatile unsigned*)&g_flags[cta << 3]);
    __syncthreads();
    for (int t = 0; t < SL; t++) {
        const float* hs = g_h[t & 1];
        for (int i = tid; i < H; i += TPB) sh[i] = __ldcg(hs + i);
        __syncthreads();
        float4 hr[8];
#pragma unroll
        for (int q = 0; q < 8; q++) hr[q] = *(const float4*)(sh + ((lane + (q << 5)) << 2));
#pragma unroll
        for (int j = 0; j < 4; j++) {
            int r = (w << 2) + j;
            const float* row = sW + r * H;
            float a = 0.f;
#pragma unroll
            for (int q = 0; q < 8; q++)
                a = dot4(*(const float4*)(row + ((lane + (q << 5)) << 2)), hr[q], a);
            a = warp_sum(a);
            if (lane == 0)
                sg[r] = a + g_xih[(size_t)t * H4 + ((r >> 3) << 10) + (cta << 3) + (r & 7)];
        }
        __syncthreads();
        if (tid < 8) {
            int hx = (cta << 3) + tid;
            float gi = sg[tid], gf = sg[8 + tid], gg = sg[16 + tid], go = sg[24 + tid];
            float cn = sigf(gf) * g_c[hx] + sigf(gi) * tanhf(gg);
            float hn = sigf(go) * tanhf(cn);
            g_c[hx] = cn; g_h[(t + 1) & 1][hx] = hn; g_eo[(size_t)t * H + hx] = hn;
        }
        gridbar(cta, ++gen);
    }
}

// ---------- decoder: persistent, 2 barriers/step ----------
__global__ void __launch_bounds__(TPB, 1) k_dec(
    const float* __restrict__ Whh, const float* __restrict__ We,
    const float* __restrict__ W2,  const float* __restrict__ av,
    const float* __restrict__ abe, const float* __restrict__ w2b)
{
    extern __shared__ float sm[];
    float* sW = sm;           // 32768 : dec_Whh rows
    float* sE = sm + 32768;   //  8192 : att_We rows (8)
    float* s2 = sm + 40960;   //  8192 : w2 halves pre-summed (8 rows)
    float* sQ = sm + 49152;   //  2048 : Qt rows (32 x 64)
    float* sP = sm + 51200;   //   512 : enc_proj slice (64 x 8)
    float* sh = sm + 51712;   //  1024
    __shared__ float sa[8], sg2[32], sw[64], se[64][4], sv8[8], sb8[8], s2b[8];
    const int cta = blockIdx.x, tid = threadIdx.x, w = tid >> 5, lane = tid & 31;

    for (int i = tid; i < 8192; i += TPB) {
        int lr = i >> 8, c4 = i & 255, g = lr >> 3, k = lr & 7;
        *(float4*)(sW + lr * H + (c4 << 2)) =
            *(const float4*)(Whh + (((size_t)((g << 10) + (cta << 3) + k)) << 10) + (c4 << 2));
    }
    for (int i = tid; i < 2048; i += TPB) {
        int r = i >> 8, c4 = i & 255;
        *(float4*)(sE + r * H + (c4 << 2)) =
            *(const float4*)(We + (((size_t)((cta << 3) + r)) << 10) + (c4 << 2));
        const float* b = W2 + (((size_t)((cta << 3) + r)) << 11);
        float4 x = *(const float4*)(b + (c4 << 2));
        float4 y = *(const float4*)(b + H + (c4 << 2));
        x.x += y.x; x.y += y.y; x.z += y.z; x.w += y.w;
        *(float4*)(s2 + r * H + (c4 << 2)) = x;
    }
    for (int i = tid; i < 2048; i += TPB) {
        int lr = i >> 6, s = i & 63;
        sQ[(lr << 6) + s] = g_Qt[((size_t)s << 12) + ((lr >> 3) << 10) + (cta << 3) + (lr & 7)];
    }
    for (int i = tid; i < 512; i += TPB)
        sP[i] = g_ep[(size_t)(i >> 3) * H + (cta << 3) + (i & 7)];
    if (tid < 8) {
        sv8[tid] = av[(cta << 3) + tid];
        sb8[tid] = abe[(cta << 3) + tid];
        s2b[tid] = w2b[(cta << 3) + tid];
    }
    unsigned gen = *((volatile unsigned*)&g_flags[cta << 3]);
    __syncthreads();

    int p = 0;
    for (int t = 0; t < TL; t++) {
        const float* hs = g_h[p];
        for (int i = tid; i < H; i += TPB) sh[i] = __ldcg(hs + i);
        __syncthreads();
        float4 hr[8];
#pragma unroll
        for (int q = 0; q < 8; q++) hr[q] = *(const float4*)(sh + ((lane + (q << 5)) << 2));
        {   // att proj row + pre row (for step t-1), both from current h
            const float* rA = sE + w * H; const float* rP = s2 + w * H;
            float aA = 0.f, aP = 0.f;
#pragma unroll
            for (int q = 0; q < 8; q++) {
                int off = (lane + (q << 5)) << 2;
                aA = dot4(*(const float4*)(rA + off), hr[q], aA);
                aP = dot4(*(const float4*)(rP + off), hr[q], aP);
            }
            aA = warp_sum(aA); aP = warp_sum(aP);
            if (lane == 0) {
                sa[w] = aA + sb8[w];
                if (t) g_pre[(size_t)(t - 1) * H + (cta << 3) + w] = aP + s2b[w];
            }
        }
        __syncthreads();
        if (tid < 64) {   // partial energy over this CTA's 8 hidden dims
            float e = 0.f;
#pragma unroll
            for (int k = 0; k < 8; k++) e += sv8[k] * tanhf(sa[k] + sP[(tid << 3) + k]);
            g_part[(tid << 7) + cta] = e;
        }
        gridbar(cta, ++gen);   // B1: partials visible
        {   // reduce 128 partials per s
            int s = tid >> 2, q = tid & 3;
            const float4* bp = (const float4*)(g_part + (s << 7) + (q << 5));
            float e = 0.f;
#pragma unroll
            for (int u = 0; u < 8; u++) { float4 v = __ldcg(bp + u); e += v.x + v.y + v.z + v.w; }
            se[s][q] = e;
        }
        __syncthreads();
        if (tid < 32) {   // softmax over 64
            float e0 = se[tid][0] + se[tid][1] + se[tid][2] + se[tid][3];
            float e1 = se[tid + 32][0] + se[tid + 32][1] + se[tid + 32][2] + se[tid + 32][3];
            float m = fmaxf(e0, e1);
#pragma unroll
            for (int o = 16; o; o >>= 1) m = fmaxf(m, __shfl_xor_sync(0xffffffffu, m, o));
            float x0 = expf(e0 - m), x1 = expf(e1 - m), s_ = x0 + x1;
#pragma unroll
            for (int o = 16; o; o >>= 1) s_ += __shfl_xor_sync(0xffffffffu, s_, o);
            float inv = 1.f / s_;
            sw[tid] = x0 * inv; sw[tid + 32] = x1 * inv;
        }
        __syncthreads();
#pragma unroll
        for (int j = 0; j < 4; j++) {   // gates = Whh@h + Qt@w + gx[t]
            int r = (w << 2) + j;
            const float* row = sW + r * H;
            float a = sQ[(r << 6) + lane] * sw[lane] + sQ[(r << 6) + 32 + lane] * sw[32 + lane];
#pragma unroll
            for (int q = 0; q < 8; q++)
                a = dot4(*(const float4*)(row + ((lane + (q << 5)) << 2)), hr[q], a);
            a = warp_sum(a);
            if (lane == 0)
                sg2[r] = a + g_gx[(size_t)t * H4 + ((r >> 3) << 10) + (cta << 3) + (r & 7)];
        }
        __syncthreads();
        if (tid < 8) {
            int hx = (cta << 3) + tid;
            float gi = sg2[tid], gf = sg2[8 + tid], gg = sg2[16 + tid], go = sg2[24 + tid];
            float cn = sigf(gf) * g_c[hx] + sigf(gi) * tanhf(gg);
            float hn = sigf(go) * tanhf(cn);
            g_c[hx] = cn; g_h[p ^ 1][hx] = hn;
        }
        gridbar(cta, ++gen);   // B2: new h visible
        p ^= 1;
    }
    // pre[T-1] from final h
    const float* hs = g_h[p];
    for (int i = tid; i < H; i += TPB) sh[i] = __ldcg(hs + i);
    __syncthreads();
    {
        const float* rP = s2 + w * H; float aP = 0.f;
#pragma unroll
        for (int q = 0; q < 8; q++) {
            int off = (lane + (q << 5)) << 2;
            aP = dot4(*(const float4*)(rP + off), *(const float4*)(sh + off), aP);
        }
        aP = warp_sum(aP);
        if (lane == 0) g_pre[(size_t)(TL - 1) * H + (cta << 3) + w] = aP + s2b[w];
    }
}

#define ENC_SMEM ((32 * 1024 + 1024) * 4)
#define DEC_SMEM (52736 * 4)

extern "C" void kernel_launch(void* const* d_in, const int* in_sizes, int n_in,
                              void* d_out, int out_size) {
    (void)in_sizes; (void)n_in; (void)out_size;
    const int*   src     = (const int*)d_in[0];
    const int*   tgt     = (const int*)d_in[1];
    const float* enc_emb = (const float*)d_in[3];
    const float* enc_Wih = (const float*)d_in[4];
    const float* enc_Whh = (const float*)d_in[5];
    const float* enc_bih = (const float*)d_in[6];
    const float* enc_bhh = (const float*)d_in[7];
    const float* dec_emb = (const float*)d_in[8];
    const float* att_We  = (const float*)d_in[9];
    const float* att_be  = (const float*)d_in[10];
    const float* att_Wu  = (const float*)d_in[11];
    const float* att_bu  = (const float*)d_in[12];
    const float* att_v   = (const float*)d_in[13];
    const float* w1_W    = (const float*)d_in[14];
    const float* w1_b    = (const float*)d_in[15];
    const float* w2_W    = (const float*)d_in[16];
    const float* w2_b    = (const float*)d_in[17];
    const float* dWih    = (const float*)d_in[18];
    const float* dWhh    = (const float*)d_in[19];
    const float* dbih    = (const float*)d_in[20];
    const float* dbhh    = (const float*)d_in[21];
    const float* out_W   = (const float*)d_in[22];
    const float* out_b   = (const float*)d_in[23];

    float *p_xe, *p_xd, *p_xih, *p_w1x, *p_gx, *p_eo, *p_ep, *p_cp, *p_Qt, *p_pre;
    int* p_dtok;
    cudaGetSymbolAddress((void**)&p_xe,  g_xe);
    cudaGetSymbolAddress((void**)&p_xd,  g_xd);
    cudaGetSymbolAddress((void**)&p_xih, g_xih);
    cudaGetSymbolAddress((void**)&p_w1x, g_w1x);
    cudaGetSymbolAddress((void**)&p_gx,  g_gx);
    cudaGetSymbolAddress((void**)&p_eo,  g_eo);
    cudaGetSymbolAddress((void**)&p_ep,  g_ep);
    cudaGetSymbolAddress((void**)&p_cp,  g_cp);
    cudaGetSymbolAddress((void**)&p_Qt,  g_Qt);
    cudaGetSymbolAddress((void**)&p_pre, g_pre);
    cudaGetSymbolAddress((void**)&p_dtok, g_dtok);

    cudaFuncSetAttribute(k_enc, cudaFuncAttributeMaxDynamicSharedMemorySize, ENC_SMEM);
    cudaFuncSetAttribute(k_dec, cudaFuncAttributeMaxDynamicSharedMemorySize, DEC_SMEM);

    k_init<<<1, 1024>>>(tgt);
    k_gather<<<SL, 256>>>(enc_emb, src, p_xe);
    k_gather<<<TL, 256>>>(dec_emb, p_dtok, p_xd);
    // xih = X_enc @ enc_Wih^T + bih + bhh
    gemm64<<<64, TPB>>>(p_xe, H, enc_Wih, H, enc_bih, enc_bhh, p_xih, H4, H);
    // w1x = X_dec @ W1x^T + w1_b   (W1x = w1_W[:, H:2H])
    gemm64<<<16, TPB>>>(p_xd, H, w1_W + H, 2 * H, w1_b, (const float*)0, p_w1x, H, H);
    // gx = w1x @ dec_Wih^T + dbih + dbhh
    gemm64<<<64, TPB>>>(p_w1x, H, dWih, H, dbih, dbhh, p_gx, H4, H);
    k_enc<<<NC, TPB, ENC_SMEM>>>(enc_Whh);
    // enc_proj = enc_outs @ att_Wu^T + att_bu
    gemm64<<<16, TPB>>>(p_eo, H, att_Wu, H, att_bu, (const float*)0, p_ep, H, H);
    // cp = enc_outs @ W1c^T   (W1c = w1_W[:, :H])
    gemm64<<<16, TPB>>>(p_eo, H, w1_W, 2 * H, (const float*)0, (const float*)0, p_cp, H, H);
    // Qt = cp @ dec_Wih^T
    gemm64<<<64, TPB>>>(p_cp, H, dWih, H, (const float*)0, (const float*)0, p_Qt, H4, H);
    k_dec<<<NC, TPB, DEC_SMEM>>>(dWhh, att_We, w2_W, att_v, att_be, w2_b);
    // logits = pre @ out_W^T + out_b
    gemm64<<<V / 64, TPB>>>(p_pre, H, out_W, H, out_b, (const float*)0, (float*)d_out, V, H);
}

// round 17
// speedup vs baseline: 1.0209x; 1.0209x over previous
#include <cuda_runtime.h>
#include <math.h>

#define H   1024
#define H4  4096
#define SL  64
#define TL  64
#define V   32000
#define NC  128
#define TPB 256
#define KT  32

// ---------- device scratch (statics only; no allocation) ----------
__device__ __align__(16) float g_xe[SL * H];
__device__ __align__(16) float g_xd[TL * H];
__device__ __align__(16) float g_xih[SL * H4];
__device__ __align__(16) float g_st[128 * H];    // rows 0-63: w1x(+b); rows 64-127: cp
__device__ __align__(16) float g_gq[128 * H4];   // rows 0-63: gx (no bias); rows 64-127: Qt
__device__ __align__(16) float g_eo[SL * H];     // encoder outputs
__device__ __align__(16) float g_ep[SL * H];     // att_Wu@enc_outs + att_bu
__device__ __align__(16) float g_pre[TL * H];
__device__ __align__(16) float g_h[2][H];
__device__ __align__(16) float g_c[H];
__device__ __align__(16) float g_part[SL * NC];
__device__ int      g_dtok[TL];
__device__ unsigned g_flags[NC * 8];

// ---------- helpers ----------
__device__ __forceinline__ float sigf(float x) { return 1.f / (1.f + expf(-x)); }
__device__ __forceinline__ float dot4(float4 a, float4 b, float acc) {
    acc = fmaf(a.x, b.x, acc); acc = fmaf(a.y, b.y, acc);
    acc = fmaf(a.z, b.z, acc); acc = fmaf(a.w, b.w, acc);
    return acc;
}
__device__ __forceinline__ float warp_sum(float v) {
#pragma unroll
    for (int o = 16; o; o >>= 1) v += __shfl_down_sync(0xffffffffu, v, o);
    return v;
}
__device__ __forceinline__ void ffma2(unsigned long long& d, unsigned long long a,
                                      unsigned long long b) {
    asm("fma.rn.f32x2 %0, %1, %2, %0;" : "+l"(d) : "l"(a), "l"(b));
}
__device__ __forceinline__ void gridbar(int cta, unsigned gen) {
    __syncthreads();
    if (threadIdx.x == 0) {
        __threadfence();
        *((volatile unsigned*)&g_flags[cta << 3]) = gen;
    }
    if (threadIdx.x < NC)
        while (*((volatile unsigned*)&g_flags[threadIdx.x << 3]) < gen) {}
    __threadfence();
    __syncthreads();
}

// ---------- init ----------
__global__ void k_init(const int* __restrict__ tgt) {
    int i = threadIdx.x;
    if (i < H)  { g_h[0][i] = 0.f; g_c[i] = 0.f; }
    if (i < TL) g_dtok[i] = i ? tgt[i - 1] : 0;   // BOS_ID = 0
    if (i < NC) g_flags[i << 3] = 0u;
}

__global__ void k_gather(const float* __restrict__ emb, const int* __restrict__ toks,
                         float* __restrict__ X) {
    int t = blockIdx.x;
    const float* s = emb + (size_t)toks[t] * H;
    for (int i = threadIdx.x; i < H; i += blockDim.x) X[t * H + i] = s[i];
}

// ---------- tiled GEMM: C[m0+m][n0+n] = A[m][:] . B[n][:] (+b1+b2 per n) ----------
// 64x64 tile per CTA, KT=32, double-buffered, f32x2 packed FMAs (B duplicated in smem).
#define GT_SMEM ((2 * KT * 68 + 2 * KT * 132) * 4)
__global__ void __launch_bounds__(TPB) gemmT(
    const float* __restrict__ A, int lda, const float* __restrict__ B, int ldb,
    const float* __restrict__ b1, const float* __restrict__ b2,
    float* __restrict__ C, int ldc, int K)
{
    extern __shared__ float sm[];
    float (*As)[KT][68]  = (float(*)[KT][68])sm;
    float (*Bs)[KT][132] = (float(*)[KT][132])(sm + 2 * KT * 68);
    const int n0 = blockIdx.x << 6, m0 = blockIdx.y << 6;
    const int tid = threadIdx.x, ti = tid & 15, tj = tid >> 4;
    const int r0 = tid >> 3, kq = tid & 7;        // float4 fill index

    unsigned long long acc[2][4];
#pragma unroll
    for (int i = 0; i < 2; i++)
#pragma unroll
        for (int j = 0; j < 4; j++) acc[i][j] = 0ull;

    const float* Ap = A + (size_t)(m0 + r0) * lda + (kq << 2);
    const float* Bp = B + (size_t)(n0 + r0) * ldb + (kq << 2);
    float4 pa0 = *(const float4*)Ap;
    float4 pa1 = *(const float4*)(Ap + (size_t)32 * lda);
    float4 pb0 = *(const float4*)Bp;
    float4 pb1 = *(const float4*)(Bp + (size_t)32 * ldb);

    const int NT = K >> 5;
    for (int kt = 0; kt < NT; kt++) {
        const int buf = kt & 1;
#pragma unroll
        for (int j = 0; j < 4; j++) {
            int kk = (kq << 2) + j;
            As[buf][kk][r0]              = ((const float*)&pa0)[j];
            As[buf][kk][r0 + 32]         = ((const float*)&pa1)[j];
            Bs[buf][kk][(r0 << 1)]       = ((const float*)&pb0)[j];
            Bs[buf][kk][(r0 << 1) + 1]   = ((const float*)&pb0)[j];
            Bs[buf][kk][((r0 + 32) << 1)]     = ((const float*)&pb1)[j];
            Bs[buf][kk][((r0 + 32) << 1) + 1] = ((const float*)&pb1)[j];
        }
        __syncthreads();
        if (kt + 1 < NT) {
            Ap += KT; Bp += KT;
            pa0 = *(const float4*)Ap;
            pa1 = *(const float4*)(Ap + (size_t)32 * lda);
            pb0 = *(const float4*)Bp;
            pb1 = *(const float4*)(Bp + (size_t)32 * ldb);
        }
#pragma unroll
        for (int kk = 0; kk < KT; kk++) {
            ulonglong2 av = *(const ulonglong2*)&As[buf][kk][ti << 2];
            ulonglong2 b0 = *(const ulonglong2*)&Bs[buf][kk][tj << 3];
            ulonglong2 b1v = *(const ulonglong2*)&Bs[buf][kk][(tj << 3) + 4];
            ffma2(acc[0][0], av.x, b0.x);  ffma2(acc[1][0], av.y, b0.x);
            ffma2(acc[0][1], av.x, b0.y);  ffma2(acc[1][1], av.y, b0.y);
            ffma2(acc[0][2], av.x, b1v.x); ffma2(acc[1][2], av.y, b1v.x);
            ffma2(acc[0][3], av.x, b1v.y); ffma2(acc[1][3], av.y, b1v.y);
        }
    }
    float bb[4];
#pragma unroll
    for (int j = 0; j < 4; j++) {
        int n = n0 + (tj << 2) + j;
        bb[j] = (b1 ? b1[n] : 0.f) + (b2 ? b2[n] : 0.f);
    }
#pragma unroll
    for (int mm = 0; mm < 4; mm++) {
        float4 o;
        o.x = ((float*)&acc[mm >> 1][0])[mm & 1] + bb[0];
        o.y = ((float*)&acc[mm >> 1][1])[mm & 1] + bb[1];
        o.z = ((float*)&acc[mm >> 1][2])[mm & 1] + bb[2];
        o.w = ((float*)&acc[mm >> 1][3])[mm & 1] + bb[3];
        *(float4*)&C[(size_t)(m0 + (ti << 2) + mm) * ldc + n0 + (tj << 2)] = o;
    }
}

// ---------- encoder: persistent, smem-resident Whh, 1 barrier/step ----------
__global__ void __launch_bounds__(TPB, 1) k_enc(const float* __restrict__ Whh) {
    extern __shared__ float sm[];
    float* sW = sm;            // 32 rows x 1024
    float* sh = sm + 32 * H;   // 1024
    __shared__ float sg[32];
    const int cta = blockIdx.x, tid = threadIdx.x, w = tid >> 5, lane = tid & 31;
    for (int i = tid; i < 8192; i += TPB) {
        int lr = i >> 8, c4 = i & 255, g = lr >> 3, k = lr & 7;
        *(float4*)(sW + lr * H + (c4 << 2)) =
            *(const float4*)(Whh + (((size_t)((g << 10) + (cta << 3) + k)) << 10) + (c4 << 2));
    }
    unsigned gen = *((volatile unsigned*)&g_flags[cta << 3]);
    __syncthreads();
    for (int t = 0; t < SL; t++) {
        const float* hs = g_h[t & 1];
        for (int i = tid; i < H; i += TPB) sh[i] = __ldcg(hs + i);
        __syncthreads();
        float4 hr[8];
#pragma unroll
        for (int q = 0; q < 8; q++) hr[q] = *(const float4*)(sh + ((lane + (q << 5)) << 2));
#pragma unroll
        for (int j = 0; j < 4; j++) {
            int r = (w << 2) + j;
            const float* row = sW + r * H;
            float a = 0.f;
#pragma unroll
            for (int q = 0; q < 8; q++)
                a = dot4(*(const float4*)(row + ((lane + (q << 5)) << 2)), hr[q], a);
            a = warp_sum(a);
            if (lane == 0)
                a += g_xih[(size_t)t * H4 + ((r >> 3) << 10) + (cta << 3) + (r & 7)], sg[r] = a;
        }
        __syncthreads();
        if (tid < 8) {
            int hx = (cta << 3) + tid;
            float gi = sg[tid], gf = sg[8 + tid], gg = sg[16 + tid], go = sg[24 + tid];
            float cn = sigf(gf) * g_c[hx] + sigf(gi) * tanhf(gg);
            float hn = sigf(go) * tanhf(cn);
            g_c[hx] = cn; g_h[(t + 1) & 1][hx] = hn; g_eo[(size_t)t * H + hx] = hn;
        }
        gridbar(cta, ++gen);
    }
}

// ---------- decoder: persistent, 2 barriers/step ----------
__global__ void __launch_bounds__(TPB, 1) k_dec(
    const float* __restrict__ Whh, const float* __restrict__ We,
    const float* __restrict__ W2,  const float* __restrict__ av,
    const float* __restrict__ abe, const float* __restrict__ w2b,
    const float* __restrict__ dbih, const float* __restrict__ dbhh)
{
    extern __shared__ float sm[];
    float* sW = sm;           // 32768 : dec_Whh rows
    float* sE = sm + 32768;   //  8192 : att_We rows (8)
    float* s2 = sm + 40960;   //  8192 : w2 halves pre-summed (8 rows)
    float* sQ = sm + 49152;   //  2048 : Qt rows (32 x 64)
    float* sP = sm + 51200;   //   512 : enc_proj slice (64 x 8)
    float* sh = sm + 51712;   //  1024
    __shared__ float sa[8], sg2[32], sw[64], se[64][4], sv8[8], sb8[8], s2b[8], sgb[32];
    const int cta = blockIdx.x, tid = threadIdx.x, w = tid >> 5, lane = tid & 31;

    for (int i = tid; i < 8192; i += TPB) {
        int lr = i >> 8, c4 = i & 255, g = lr >> 3, k = lr & 7;
        *(float4*)(sW + lr * H + (c4 << 2)) =
            *(const float4*)(Whh + (((size_t)((g << 10) + (cta << 3) + k)) << 10) + (c4 << 2));
    }
    for (int i = tid; i < 2048; i += TPB) {
        int r = i >> 8, c4 = i & 255;
        *(float4*)(sE + r * H + (c4 << 2)) =
            *(const float4*)(We + (((size_t)((cta << 3) + r)) << 10) + (c4 << 2));
        const float* b = W2 + (((size_t)((cta << 3) + r)) << 11);
        float4 x = *(const float4*)(b + (c4 << 2));
        float4 y = *(const float4*)(b + H + (c4 << 2));
        x.x += y.x; x.y += y.y; x.z += y.z; x.w += y.w;
        *(float4*)(s2 + r * H + (c4 << 2)) = x;
    }
    for (int i = tid; i < 2048; i += TPB) {
        int lr = i >> 6, s = i & 63;
        sQ[(lr << 6) + s] =
            g_gq[((size_t)(64 + s) << 12) + ((lr >> 3) << 10) + (cta << 3) + (lr & 7)];
    }
    for (int i = tid; i < 512; i += TPB)
        sP[i] = g_ep[(size_t)(i >> 3) * H + (cta << 3) + (i & 7)];
    if (tid < 8) {
        sv8[tid] = av[(cta << 3) + tid];
        sb8[tid] = abe[(cta << 3) + tid];
        s2b[tid] = w2b[(cta << 3) + tid];
    }
    if (tid < 32) {
        int gr = ((tid >> 3) << 10) + (cta << 3) + (tid & 7);
        sgb[tid] = dbih[gr] + dbhh[gr];
    }
    unsigned gen = *((volatile unsigned*)&g_flags[cta << 3]);
    __syncthreads();

    int p = 0;
    for (int t = 0; t < TL; t++) {
        const float* hs = g_h[p];
        for (int i = tid; i < H; i += TPB) sh[i] = __ldcg(hs + i);
        __syncthreads();
        float4 hr[8];
#pragma unroll
        for (int q = 0; q < 8; q++) hr[q] = *(const float4*)(sh + ((lane + (q << 5)) << 2));
        {   // att proj row + pre row (for step t-1), both from current h
            const float* rA = sE + w * H; const float* rP = s2 + w * H;
            float aA = 0.f, aP = 0.f;
#pragma unroll
            for (int q = 0; q < 8; q++) {
                int off = (lane + (q << 5)) << 2;
                aA = dot4(*(const float4*)(rA + off), hr[q], aA);
                aP = dot4(*(const float4*)(rP + off), hr[q], aP);
            }
            aA = warp_sum(aA); aP = warp_sum(aP);
            if (lane == 0) {
                sa[w] = aA + sb8[w];
                if (t) g_pre[(size_t)(t - 1) * H + (cta << 3) + w] = aP + s2b[w];
            }
        }
        __syncthreads();
        if (tid < 64) {   // partial energy over this CTA's 8 hidden dims
            float e = 0.f;
#pragma unroll
            for (int k = 0; k < 8; k++) e += sv8[k] * tanhf(sa[k] + sP[(tid << 3) + k]);
            g_part[(tid << 7) + cta] = e;
        }
        gridbar(cta, ++gen);   // B1: partials visible
        {   // reduce 128 partials per s
            int s = tid >> 2, q = tid & 3;
            const float4* bp = (const float4*)(g_part + (s << 7) + (q << 5));
            float e = 0.f;
#pragma unroll
            for (int u = 0; u < 8; u++) { float4 v = __ldcg(bp + u); e += v.x + v.y + v.z + v.w; }
            se[s][q] = e;
        }
        __syncthreads();
        if (tid < 32) {   // softmax over 64
            float e0 = se[tid][0] + se[tid][1] + se[tid][2] + se[tid][3];
            float e1 = se[tid + 32][0] + se[tid + 32][1] + se[tid + 32][2] + se[tid + 32][3];
            float m = fmaxf(e0, e1);
#pragma unroll
            for (int o = 16; o; o >>= 1) m = fmaxf(m, __shfl_xor_sync(0xffffffffu, m, o));
            float x0 = expf(e0 - m), x1 = expf(e1 - m), s_ = x0 + x1;
#pragma unroll
            for (int o = 16; o; o >>= 1) s_ += __shfl_xor_sync(0xffffffffu, s_, o);
            float inv = 1.f / s_;
            sw[tid] = x0 * inv; sw[tid + 32] = x1 * inv;
        }
        __syncthreads();
#pragma unroll
        for (int j = 0; j < 4; j++) {   // gates = Whh@h + Qt@w + gx[t] + bias
            int r = (w << 2) + j;
            const float* row = sW + r * H;
            float a = sQ[(r << 6) + lane] * sw[lane] + sQ[(r << 6) + 32 + lane] * sw[32 + lane];
#pragma unroll
            for (int q = 0; q < 8; q++)
                a = dot4(*(const float4*)(row + ((lane + (q << 5)) << 2)), hr[q], a);
            a = warp_sum(a);
            if (lane == 0)
                sg2[r] = a + g_gq[(size_t)t * H4 + ((r >> 3) << 10) + (cta << 3) + (r & 7)]
                       + sgb[r];
        }
        __syncthreads();
        if (tid < 8) {
            int hx = (cta << 3) + tid;
            float gi = sg2[tid], gf = sg2[8 + tid], gg = sg2[16 + tid], go = sg2[24 + tid];
            float cn = sigf(gf) * g_c[hx] + sigf(gi) * tanhf(gg);
            float hn = sigf(go) * tanhf(cn);
            g_c[hx] = cn; g_h[p ^ 1][hx] = hn;
        }
        gridbar(cta, ++gen);   // B2: new h visible
        p ^= 1;
    }
    // pre[T-1] from final h
    const float* hs = g_h[p];
    for (int i = tid; i < H; i += TPB) sh[i] = __ldcg(hs + i);
    __syncthreads();
    {
        const float* rP = s2 + w * H; float aP = 0.f;
#pragma unroll
        for (int q = 0; q < 8; q++) {
            int off = (lane + (q << 5)) << 2;
            aP = dot4(*(const float4*)(rP + off), *(const float4*)(sh + off), aP);
        }
        aP = warp_sum(aP);
        if (lane == 0) g_pre[(size_t)(TL - 1) * H + (cta << 3) + w] = aP + s2b[w];
    }
}

#define ENC_SMEM ((32 * 1024 + 1024) * 4)
#define DEC_SMEM (52736 * 4)

extern "C" void kernel_launch(void* const* d_in, const int* in_sizes, int n_in,
                              void* d_out, int out_size) {
    (void)in_sizes; (void)n_in; (void)out_size;
    const int*   src     = (const int*)d_in[0];
    const int*   tgt     = (const int*)d_in[1];
    const float* enc_emb = (const float*)d_in[3];
    const float* enc_Wih = (const float*)d_in[4];
    const float* enc_Whh = (const float*)d_in[5];
    const float* enc_bih = (const float*)d_in[6];
    const float* enc_bhh = (const float*)d_in[7];
    const float* dec_emb = (const float*)d_in[8];
    const float* att_We  = (const float*)d_in[9];
    const float* att_be  = (const float*)d_in[10];
    const float* att_Wu  = (const float*)d_in[11];
    const float* att_bu  = (const float*)d_in[12];
    const float* att_v   = (const float*)d_in[13];
    const float* w1_W    = (const float*)d_in[14];
    const float* w1_b    = (const float*)d_in[15];
    const float* w2_W    = (const float*)d_in[16];
    const float* w2_b    = (const float*)d_in[17];
    const float* dWih    = (const float*)d_in[18];
    const float* dWhh    = (const float*)d_in[19];
    const float* dbih    = (const float*)d_in[20];
    const float* dbhh    = (const float*)d_in[21];
    const float* out_W   = (const float*)d_in[22];
    const float* out_b   = (const float*)d_in[23];

    float *p_xe, *p_xd, *p_xih, *p_st, *p_gq, *p_eo, *p_ep, *p_pre;
    int* p_dtok;
    cudaGetSymbolAddress((void**)&p_xe,  g_xe);
    cudaGetSymbolAddress((void**)&p_xd,  g_xd);
    cudaGetSymbolAddress((void**)&p_xih, g_xih);
    cudaGetSymbolAddress((void**)&p_st,  g_st);
    cudaGetSymbolAddress((void**)&p_gq,  g_gq);
    cudaGetSymbolAddress((void**)&p_eo,  g_eo);
    cudaGetSymbolAddress((void**)&p_ep,  g_ep);
    cudaGetSymbolAddress((void**)&p_pre, g_pre);
    cudaGetSymbolAddress((void**)&p_dtok, g_dtok);

    cudaFuncSetAttribute(gemmT, cudaFuncAttributeMaxDynamicSharedMemorySize, GT_SMEM);
    cudaFuncSetAttribute(k_enc, cudaFuncAttributeMaxDynamicSharedMemorySize, ENC_SMEM);
    cudaFuncSetAttribute(k_dec, cudaFuncAttributeMaxDynamicSharedMemorySize, DEC_SMEM);

    k_init<<<1, 1024>>>(tgt);
    k_gather<<<SL, 256>>>(enc_emb, src, p_xe);
    k_gather<<<TL, 256>>>(dec_emb, p_dtok, p_xd);
    // xih = X_enc @ enc_Wih^T + bih + bhh
    gemmT<<<dim3(64, 1), TPB, GT_SMEM>>>(p_xe, H, enc_Wih, H, enc_bih, enc_bhh, p_xih, H4, H);
    // w1x(+b) = X_dec @ W1x^T + w1_b   -> g_st rows 0-63
    gemmT<<<dim3(16, 1), TPB, GT_SMEM>>>(p_xd, H, w1_W + H, 2 * H, w1_b, (const float*)0,
                                         p_st, H, H);
    k_enc<<<NC, TPB, ENC_SMEM>>>(enc_Whh);
    // enc_proj = enc_outs @ att_Wu^T + att_bu
    gemmT<<<dim3(16, 1), TPB, GT_SMEM>>>(p_eo, H, att_Wu, H, att_bu, (const float*)0,
                                         p_ep, H, H);
    // cp = enc_outs @ W1c^T -> g_st rows 64-127
    gemmT<<<dim3(16, 1), TPB, GT_SMEM>>>(p_eo, H, w1_W, 2 * H, (const float*)0, (const float*)0,
                                         p_st + 64 * H, H, H);
    // [gx; Qt] = [w1x; cp] @ dec_Wih^T  (no bias; dec adds dbih+dbhh to gx rows)
    gemmT<<<dim3(64, 2), TPB, GT_SMEM>>>(p_st, H, dWih, H, (const float*)0, (const float*)0,
                                         p_gq, H4, H);
    k_dec<<<NC, TPB, DEC_SMEM>>>(dWhh, att_We, w2_W, att_v, att_be, w2_b, dbih, dbhh);
    // logits = pre @ out_W^T + out_b
    gemmT<<<dim3(V / 64, 1), TPB, GT_SMEM>>>(p_pre, H, out_W, H, out_b, (const float*)0,
                                             (float*)d_out, V, H);
}